// round 7
// baseline (speedup 1.0000x reference)
#include <cuda_runtime.h>

#define BB   64
#define TT   128
#define HH   256
#define INN  256
#define VV   256
#define NDLY 32
#define BH   (BB*HH)
#define GRID 128

__device__ float    g_cw[NDLY*HH*INN];
__device__ float    g_xw[BB*TT*HH];
__device__ float    g_wa1[INN*HH];
__device__ float    g_hist[BB*NDLY*HH];
__device__ float    g_partial[NDLY*BB*HH];
__device__ unsigned g_keys[2*BB];
__device__ int      g_tau[BB], g_done[BB], g_stepsA[BB], g_curIdx[BB];
__device__ unsigned g_barC, g_barP;

// ---- packed f32x2 helpers ----
__device__ __forceinline__ unsigned long long pkf2(float lo, float hi) {
    unsigned long long r;
    asm("mov.b64 %0, {%1, %2};" : "=l"(r) : "f"(lo), "f"(hi));
    return r;
}
__device__ __forceinline__ float2 upkf2(unsigned long long v) {
    float2 r;
    asm("mov.b64 {%0, %1}, %2;" : "=f"(r.x), "=f"(r.y) : "l"(v));
    return r;
}
__device__ __forceinline__ unsigned long long ffma2(unsigned long long a,
                                                    unsigned long long b,
                                                    unsigned long long c) {
    unsigned long long d;
    asm("fma.rn.f32x2 %0, %1, %2, %3;" : "=l"(d) : "l"(a), "l"(b), "l"(c));
    return d;
}

// XLA/Eigen f32 tanh
__device__ __forceinline__ float xla_tanh(float x) {
    if (fabsf(x) < 0.0004f) return x;
    float cx = fminf(fmaxf(x, -7.90531110763549805f), 7.90531110763549805f);
    float x2 = cx * cx;
    float p = fmaf(x2, -2.76076847742355e-16f, 2.00018790482477e-13f);
    p = fmaf(x2, p, -8.60467152213735e-11f);
    p = fmaf(x2, p,  5.12229709037114e-08f);
    p = fmaf(x2, p,  1.48572235717979e-05f);
    p = fmaf(x2, p,  6.37261928875436e-04f);
    p = fmaf(x2, p,  4.89352455891786e-03f);
    p = cx * p;
    float q = fmaf(x2, 1.19825839466702e-06f, 1.18534705686654e-04f);
    q = fmaf(x2, q, 2.26843463243900e-03f);
    q = fmaf(x2, q, 4.89352518554385e-03f);
    return p / q;
}

__device__ __forceinline__ void tf2x32(unsigned k0, unsigned k1,
                                       unsigned x0, unsigned x1,
                                       unsigned &o0, unsigned &o1) {
    unsigned ks2 = k0 ^ k1 ^ 0x1BD11BDAu;
    x0 += k0; x1 += k1;
#define TF_R(r) { x0 += x1; x1 = (x1 << (r)) | (x1 >> (32 - (r))); x1 ^= x0; }
    TF_R(13) TF_R(15) TF_R(26) TF_R(6)
    x0 += k1;  x1 += ks2 + 1u;
    TF_R(17) TF_R(29) TF_R(16) TF_R(24)
    x0 += ks2; x1 += k0 + 2u;
    TF_R(13) TF_R(15) TF_R(26) TF_R(6)
    x0 += k0;  x1 += k1 + 3u;
    TF_R(17) TF_R(29) TF_R(16) TF_R(24)
    x0 += k1;  x1 += ks2 + 4u;
    TF_R(13) TF_R(15) TF_R(26) TF_R(6)
    x0 += ks2; x1 += k0 + 5u;
#undef TF_R
    o0 = x0; o1 = x1;
}

// grid-wide barrier (all GRID CTAs co-resident: GRID=128 <= 148 SMs, 1 CTA/SM)
__device__ __forceinline__ void gsync(unsigned &ph) {
    __syncthreads();
    if (threadIdx.x == 0) {
        __threadfence();
        if (atomicAdd(&g_barC, 1u) == GRID - 1u) {
            g_barC = 0u;
            __threadfence();
            atomicExch(&g_barP, ph + 1u);
        } else {
            while (*(volatile unsigned*)&g_barP < ph + 1u) {}
        }
        __threadfence();
    }
    ph++;
    __syncthreads();
}

__global__ void init_state_kernel() {
    int i = blockIdx.x * blockDim.x + threadIdx.x;
    if (i < BB * NDLY * HH) g_hist[i] = 0.0f;
    if (i < BB) { g_tau[i] = 0; g_done[i] = 0; g_stepsA[i] = 0; g_curIdx[i] = -1; }
    if (i == 0) { g_barC = 0u; g_barP = 0u; }
}

// split(key(42), 64), partitionable: child_b = cipher(key, (0, b))
__global__ void keys_kernel() {
    int tid = threadIdx.x;
    if (tid < BB) {
        unsigned o0, o1;
        tf2x32(0u, 42u, 0u, (unsigned)tid, o0, o1);
        g_keys[2 * tid]     = o0;
        g_keys[2 * tid + 1] = o1;
    }
}

__global__ void build_cw_kernel(const float* __restrict__ lateral,
                                const float* __restrict__ tau) {
    int i = blockIdx.x * 256 + threadIdx.x;
    int dd = i >> 16;
    int hi = i & 65535;
    const float INV = 0.0625f, INV2 = 0.0625f * 0.0625f;
    float tc = fminf(fmaxf(tau[hi], 1.0f), 32.0f);
    float t1 = ((float)(dd + 1) - tc) * INV2;
    float c  = fmaxf(0.0f, INV - fabsf(t1));
    g_cw[i] = c * lateral[hi];
}

__global__ void build_aux_kernel(const float* __restrict__ w_aff,
                                 const float* __restrict__ b_aff) {
    int i = blockIdx.x * 256 + threadIdx.x;
    int a = i / HH, h2 = i % HH;
    g_wa1[i] = w_aff[h2 * INN + a] + b_aff[h2];
}

// xw[m][h] = sum_i x[m][i]*w_aff[h][i] + b_aff[h]
__global__ __launch_bounds__(256) void xw_gemm_kernel(
        const float* __restrict__ x, const float* __restrict__ w_aff,
        const float* __restrict__ b_aff) {
    __shared__ float As[32][65], Ws[32][65];
    int m0 = blockIdx.x * 64, h0 = blockIdx.y * 64;
    int tid = threadIdx.x, tx = tid % 16, ty = tid / 16;
    float acc[4][4] = {{0}};
    for (int k0 = 0; k0 < INN; k0 += 32) {
        int r = tid >> 2, kq = tid & 3;
#pragma unroll
        for (int j = 0; j < 8; j++) {
            As[kq * 8 + j][r] = x[(size_t)(m0 + r) * INN + k0 + kq * 8 + j];
            Ws[kq * 8 + j][r] = w_aff[(h0 + r) * INN + k0 + kq * 8 + j];
        }
        __syncthreads();
#pragma unroll
        for (int k = 0; k < 32; k++) {
            float av[4], bv[4];
#pragma unroll
            for (int u = 0; u < 4; u++) av[u] = As[k][ty * 4 + u];
#pragma unroll
            for (int v = 0; v < 4; v++) bv[v] = Ws[k][tx * 4 + v];
#pragma unroll
            for (int u = 0; u < 4; u++)
#pragma unroll
                for (int v = 0; v < 4; v++)
                    acc[u][v] = fmaf(av[u], bv[v], acc[u][v]);
        }
        __syncthreads();
    }
#pragma unroll
    for (int u = 0; u < 4; u++)
#pragma unroll
        for (int v = 0; v < 4; v++) {
            int m = m0 + ty * 4 + u, h = h0 + tx * 4 + v;
            g_xw[(size_t)m * HH + h] = acc[u][v] + b_aff[h];
        }
}

// ---------------- persistent step kernel -----------------------------------
// 128 CTAs: CTA = (dd, h-block). Per step: K1 (delay-gemm) -> gsync ->
// K2 (CTAs 0..63, one sample each) -> gsync.
__global__ __launch_bounds__(256) void persistent_kernel(
        const int* __restrict__ lengths, const float* __restrict__ w_eff,
        const float* __restrict__ b_eff, float* __restrict__ out,
        int N, int writeSteps) {
    extern __shared__ unsigned long long Asd[];   // [256 k][64 h] dup-packed
    __shared__ float Bs[32][66];
    __shared__ int   rowOff[BB];
    __shared__ __align__(16) float sh_hdel[HH];
    __shared__ float sval[VV];
    __shared__ int   sidx[VV];

    int tid = threadIdx.x, cta = blockIdx.x;
    int dd = cta >> 2, hb = cta & 3, h0 = hb * 64;
    int tx = tid & 15, ty = tid >> 4;
    int r = tid >> 2, kq = tid & 3;

    // one-time: pack this CTA's cw tile into smem (reused all 262 steps)
    {
        const float* cwd = g_cw + (size_t)dd * HH * INN;
        for (int idx = tid; idx < 64 * 256; idx += 256) {
            int hl = idx >> 8, k = idx & 255;
            float a = cwd[(size_t)(h0 + hl) * INN + k];
            Asd[(size_t)k * 64 + hl] = pkf2(a, a);
        }
    }
    __syncthreads();

    int lenb = (cta < BB) ? lengths[cta] : 0;
    unsigned ph = 0;
    int TS = TT + 9 + N;

    for (int step = 0; step < TS; step++) {
        // ---- K1: partial[dd][b][h0..h0+63] ----
        if (tid < BB) {
            int tb = __ldcg(&g_tau[tid]);
            rowOff[tid] = tid * (NDLY * HH) + (((tb - (dd + 1)) & 31) * HH);
        }
        __syncthreads();
        unsigned long long acc[4][2];
#pragma unroll
        for (int u = 0; u < 4; u++) { acc[u][0] = 0ull; acc[u][1] = 0ull; }
        int brow = rowOff[r];
        for (int k0 = 0; k0 < 256; k0 += 32) {
            const float4* bp = (const float4*)(g_hist + brow + k0 + kq * 8);
            float4 bv0 = __ldcg(bp);
            float4 bv1 = __ldcg(bp + 1);
            if (k0) __syncthreads();
            float bv[8] = {bv0.x, bv0.y, bv0.z, bv0.w, bv1.x, bv1.y, bv1.z, bv1.w};
#pragma unroll
            for (int j = 0; j < 8; j++) Bs[kq * 8 + j][r] = bv[j];
            __syncthreads();
#pragma unroll
            for (int k = 0; k < 32; k++) {
                const unsigned long long* arow = &Asd[(size_t)(k0 + k) * 64];
                unsigned long long a0p = arow[ty * 4 + 0];
                unsigned long long a1p = arow[ty * 4 + 1];
                unsigned long long a2p = arow[ty * 4 + 2];
                unsigned long long a3p = arow[ty * 4 + 3];
                const unsigned long long* bp2 = (const unsigned long long*)&Bs[k][0];
                unsigned long long bb0 = bp2[tx * 2 + 0];
                unsigned long long bb1 = bp2[tx * 2 + 1];
                acc[0][0] = ffma2(a0p, bb0, acc[0][0]);
                acc[1][0] = ffma2(a1p, bb0, acc[1][0]);
                acc[2][0] = ffma2(a2p, bb0, acc[2][0]);
                acc[3][0] = ffma2(a3p, bb0, acc[3][0]);
                acc[0][1] = ffma2(a0p, bb1, acc[0][1]);
                acc[1][1] = ffma2(a1p, bb1, acc[1][1]);
                acc[2][1] = ffma2(a2p, bb1, acc[2][1]);
                acc[3][1] = ffma2(a3p, bb1, acc[3][1]);
            }
        }
        {
            float* P = g_partial + (size_t)dd * BH;
#pragma unroll
            for (int u = 0; u < 4; u++)
#pragma unroll
                for (int v2 = 0; v2 < 2; v2++) {
                    float2 val = upkf2(acc[u][v2]);
                    int bcol = tx * 4 + v2 * 2;
                    P[(bcol + 0) * HH + h0 + ty * 4 + u] = val.x;
                    P[(bcol + 1) * HH + h0 + ty * 4 + u] = val.y;
                }
        }
        gsync(ph);

        // ---- K2: per-sample update (CTAs 0..63) ----
        if (cta < BB) {
            int b = cta;
            float acc2 = 0.0f;
            for (int s = NDLY - 1; s >= 0; --s)
                acc2 += __ldcg(&g_partial[(size_t)s * BH + b * HH + tid]);

            if (step < TT) {                 // encoder
                int t = step;
                float hv = xla_tanh(g_xw[(size_t)(b * TT + t) * HH + tid] + acc2);
                if (t < lenb) {
                    g_hist[b * (NDLY * HH) + (t & 31) * HH + tid] = hv;
                    if (tid == 0) g_tau[b] = t + 1;
                }
            } else {                         // think/decode
                int g = step - TT;
                int ci = g_curIdx[b], myTau = g_tau[b], myDone = g_done[b];
                int mySteps = g_stepsA[b];

                sh_hdel[tid] = acc2;
                __syncthreads();

                const unsigned long long* wrow =
                    (const unsigned long long*)(w_eff + (size_t)tid * HH);
                const unsigned long long* hdl = (const unsigned long long*)sh_hdel;
                unsigned long long y2 = 0ull;
#pragma unroll 16
                for (int h2 = 0; h2 < HH / 2; h2++)
                    y2 = ffma2(wrow[h2], hdl[h2], y2);
                float2 yp = upkf2(y2);
                float y = yp.x + yp.y + b_eff[tid];

                unsigned kv = (g < 9) ? (unsigned)g : (unsigned)(1000 + (g - 9));
                unsigned f0, f1;
                tf2x32(g_keys[2 * b], g_keys[2 * b + 1], 0u, kv, f0, f1);
                unsigned o0, o1;
                tf2x32(f0, f1, 0u, (unsigned)tid, o0, o1);
                unsigned bits = o0 ^ o1;

                const float TINY = 1.17549435e-38f;
                float fm = __uint_as_float((bits >> 9) | 0x3F800000u) - 1.0f;
                float uu = fmaxf(TINY, fm * (1.0f - TINY) + TINY);
                float gum = -logf(-logf(uu));

                sval[tid] = y + gum; sidx[tid] = tid;
                __syncthreads();
                for (int off = 128; off > 0; off >>= 1) {
                    if (tid < off) {
                        float v2 = sval[tid + off]; int i2 = sidx[tid + off];
                        if (v2 > sval[tid] || (v2 == sval[tid] && i2 < sidx[tid])) {
                            sval[tid] = v2; sidx[tid] = i2;
                        }
                    }
                    __syncthreads();
                }
                int amax = sidx[0];

                float xin = (ci < 0) ? g_xw[(size_t)(b * TT + (lenb - 1)) * HH + tid]
                                     : g_wa1[ci * HH + tid];
                float hv = xla_tanh(xin + sh_hdel[tid]);

                bool thinkPh = (g < 9);
                bool adv = thinkPh ? (myDone == 0) : true;
                if (adv) g_hist[b * (NDLY * HH) + (myTau & 31) * HH + tid] = hv;

                if (!thinkPh) {
                    int k = g - 9;
                    if (tid < VV - 1)
                        out[((size_t)b * N + k) * (VV - 1) + tid] = y;
                }
                if (tid == 0) {
                    if (thinkPh) {
                        int nst = mySteps + (myDone ? 0 : 1);
                        int nd = (myDone || amax == (VV - 1) || nst > 8) ? 1 : 0;
                        g_stepsA[b] = nst; g_done[b] = nd;
                        if (!myDone) { g_tau[b] = myTau + 1; g_curIdx[b] = amax; }
                        if (g == 8 && writeSteps)
                            out[(size_t)BB * N * (VV - 1) + b] = (float)nst;
                    } else {
                        g_tau[b] = myTau + 1; g_curIdx[b] = amax;
                    }
                }
            }
        }
        gsync(ph);
    }
}

extern "C" void kernel_launch(void* const* d_in, const int* in_sizes, int n_in,
                              void* d_out, int out_size) {
    const float* x       = (const float*)d_in[0];
    const float* w_aff   = (const float*)d_in[1];
    const float* b_aff   = (const float*)d_in[2];
    const float* lateral = (const float*)d_in[3];
    const float* tau     = (const float*)d_in[4];
    const float* w_eff   = (const float*)d_in[5];
    const float* b_eff   = (const float*)d_in[6];
    const int*   lengths = (const int*)d_in[7];
    (void)n_in; (void)in_sizes;
    float* out = (float*)d_out;

    int Vm1 = VV - 1;
    int N, writeSteps;
    if (out_size % (BB * Vm1) == 0) { N = out_size / (BB * Vm1); writeSteps = 0; }
    else { N = (out_size - BB) / (BB * Vm1); writeSteps = 1; }

    static int smemSet = 0;
    if (!smemSet) {
        cudaFuncSetAttribute(persistent_kernel,
                             cudaFuncAttributeMaxDynamicSharedMemorySize,
                             131072);
        smemSet = 1;
    }

    init_state_kernel<<<(BB * NDLY * HH + 255) / 256, 256>>>();
    keys_kernel<<<1, 64>>>();
    build_cw_kernel<<<(NDLY * HH * INN) / 256, 256>>>(lateral, tau);
    build_aux_kernel<<<(INN * HH) / 256, 256>>>(w_aff, b_aff);
    xw_gemm_kernel<<<dim3((BB * TT) / 64, HH / 64), 256>>>(x, w_aff, b_aff);

    persistent_kernel<<<GRID, 256, 131072>>>(lengths, w_eff, b_eff, out,
                                             N, writeSteps);
}

// round 9
// speedup vs baseline: 1.2866x; 1.2866x over previous
#include <cuda_runtime.h>

#define BB   64
#define TT   128
#define HH   256
#define INN  256
#define VV   256
#define NDLY 32
#define BH   (BB*HH)
#define GRID 128
typedef unsigned long long ull;

__device__ float    g_cw[NDLY*HH*INN];
__device__ float    g_xw[BB*TT*HH];
__device__ float    g_wa1[INN*HH];
__device__ ull      g_weT2[(HH/2)*VV];     // [h2][v] packed {w[v][2h2], w[v][2h2+1]}
__device__ float    g_hist[BB*NDLY*HH];
__device__ float    g_partial[NDLY*BB*HH];
__device__ unsigned g_keys[2*BB];
__device__ int      g_tau[BB], g_done[BB], g_stepsA[BB], g_curIdx[BB];
__device__ unsigned g_cnt1[8*32];          // 8 group counters, 128B apart
__device__ unsigned g_cnt2;
__device__ unsigned g_phase;

// ---- packed f32x2 helpers ----
__device__ __forceinline__ ull pkf2(float lo, float hi) {
    ull r; asm("mov.b64 %0, {%1, %2};" : "=l"(r) : "f"(lo), "f"(hi)); return r;
}
__device__ __forceinline__ float2 upkf2(ull v) {
    float2 r; asm("mov.b64 {%0, %1}, %2;" : "=f"(r.x), "=f"(r.y) : "l"(v)); return r;
}
__device__ __forceinline__ ull ffma2(ull a, ull b, ull c) {
    ull d; asm("fma.rn.f32x2 %0, %1, %2, %3;" : "=l"(d) : "l"(a), "l"(b), "l"(c));
    return d;
}

// XLA/Eigen f32 tanh
__device__ __forceinline__ float xla_tanh(float x) {
    if (fabsf(x) < 0.0004f) return x;
    float cx = fminf(fmaxf(x, -7.90531110763549805f), 7.90531110763549805f);
    float x2 = cx * cx;
    float p = fmaf(x2, -2.76076847742355e-16f, 2.00018790482477e-13f);
    p = fmaf(x2, p, -8.60467152213735e-11f);
    p = fmaf(x2, p,  5.12229709037114e-08f);
    p = fmaf(x2, p,  1.48572235717979e-05f);
    p = fmaf(x2, p,  6.37261928875436e-04f);
    p = fmaf(x2, p,  4.89352455891786e-03f);
    p = cx * p;
    float q = fmaf(x2, 1.19825839466702e-06f, 1.18534705686654e-04f);
    q = fmaf(x2, q, 2.26843463243900e-03f);
    q = fmaf(x2, q, 4.89352518554385e-03f);
    return p / q;
}

__device__ __forceinline__ void tf2x32(unsigned k0, unsigned k1,
                                       unsigned x0, unsigned x1,
                                       unsigned &o0, unsigned &o1) {
    unsigned ks2 = k0 ^ k1 ^ 0x1BD11BDAu;
    x0 += k0; x1 += k1;
#define TF_R(r) { x0 += x1; x1 = (x1 << (r)) | (x1 >> (32 - (r))); x1 ^= x0; }
    TF_R(13) TF_R(15) TF_R(26) TF_R(6)
    x0 += k1;  x1 += ks2 + 1u;
    TF_R(17) TF_R(29) TF_R(16) TF_R(24)
    x0 += ks2; x1 += k0 + 2u;
    TF_R(13) TF_R(15) TF_R(26) TF_R(6)
    x0 += k0;  x1 += k1 + 3u;
    TF_R(17) TF_R(29) TF_R(16) TF_R(24)
    x0 += k1;  x1 += ks2 + 4u;
    TF_R(13) TF_R(15) TF_R(26) TF_R(6)
    x0 += ks2; x1 += k0 + 5u;
#undef TF_R
    o0 = x0; o1 = x1;
}

// two-level grid barrier: 8 group counters (16 arrivals each) + root (8)
__device__ __forceinline__ void gsync(unsigned &ph) {
    __syncthreads();
    if (threadIdx.x == 0) {
        __threadfence();
        unsigned o = atomicAdd(&g_cnt1[(blockIdx.x >> 4) * 32], 1u);
        if (o == 15u) {
            unsigned o2 = atomicAdd(&g_cnt2, 1u);
            if (o2 == 7u) {
                g_cnt2 = 0u;
#pragma unroll
                for (int i = 0; i < 8; i++) g_cnt1[i * 32] = 0u;
                __threadfence();
                *(volatile unsigned*)&g_phase = ph + 1u;
            }
        }
        while (*(volatile unsigned*)&g_phase < ph + 1u) { }
        __threadfence();
    }
    ph++;
    __syncthreads();
}

__global__ void init_state_kernel() {
    int i = blockIdx.x * blockDim.x + threadIdx.x;
    if (i < BB * NDLY * HH) g_hist[i] = 0.0f;
    if (i < BB) { g_tau[i] = 0; g_done[i] = 0; g_stepsA[i] = 0; g_curIdx[i] = -1; }
    if (i < 8 * 32) g_cnt1[i] = 0u;
    if (i == 0) { g_cnt2 = 0u; g_phase = 0u; }
}

// split(key(42), 64), partitionable: child_b = cipher(key, (0, b))
__global__ void keys_kernel() {
    int tid = threadIdx.x;
    if (tid < BB) {
        unsigned o0, o1;
        tf2x32(0u, 42u, 0u, (unsigned)tid, o0, o1);
        g_keys[2 * tid]     = o0;
        g_keys[2 * tid + 1] = o1;
    }
}

__global__ void build_cw_kernel(const float* __restrict__ lateral,
                                const float* __restrict__ tau) {
    int i = blockIdx.x * 256 + threadIdx.x;
    int dd = i >> 16;
    int hi = i & 65535;
    const float INV = 0.0625f, INV2 = 0.0625f * 0.0625f;
    float tc = fminf(fmaxf(tau[hi], 1.0f), 32.0f);
    float t1 = ((float)(dd + 1) - tc) * INV2;
    float c  = fmaxf(0.0f, INV - fabsf(t1));
    g_cw[i] = c * lateral[hi];
}

__global__ void build_aux_kernel(const float* __restrict__ w_aff,
                                 const float* __restrict__ b_aff,
                                 const float* __restrict__ w_eff) {
    int i = blockIdx.x * 256 + threadIdx.x;        // 65536
    int a = i / HH, h2a = i % HH;
    g_wa1[i] = w_aff[h2a * INN + a] + b_aff[h2a];
    if (i < (HH / 2) * VV) {
        int h2 = i / VV, v = i % VV;
        g_weT2[i] = pkf2(w_eff[v * HH + 2 * h2], w_eff[v * HH + 2 * h2 + 1]);
    }
}

// xw[m][h] = sum_i x[m][i]*w_aff[h][i] + b_aff[h]
__global__ __launch_bounds__(256) void xw_gemm_kernel(
        const float* __restrict__ x, const float* __restrict__ w_aff,
        const float* __restrict__ b_aff) {
    __shared__ float As[32][65], Ws[32][65];
    int m0 = blockIdx.x * 64, h0 = blockIdx.y * 64;
    int tid = threadIdx.x, tx = tid % 16, ty = tid / 16;
    float acc[4][4] = {{0}};
    for (int k0 = 0; k0 < INN; k0 += 32) {
        int r = tid >> 2, kq = tid & 3;
#pragma unroll
        for (int j = 0; j < 8; j++) {
            As[kq * 8 + j][r] = x[(size_t)(m0 + r) * INN + k0 + kq * 8 + j];
            Ws[kq * 8 + j][r] = w_aff[(h0 + r) * INN + k0 + kq * 8 + j];
        }
        __syncthreads();
#pragma unroll
        for (int k = 0; k < 32; k++) {
            float av[4], bv[4];
#pragma unroll
            for (int u = 0; u < 4; u++) av[u] = As[k][ty * 4 + u];
#pragma unroll
            for (int v = 0; v < 4; v++) bv[v] = Ws[k][tx * 4 + v];
#pragma unroll
            for (int u = 0; u < 4; u++)
#pragma unroll
                for (int v = 0; v < 4; v++)
                    acc[u][v] = fmaf(av[u], bv[v], acc[u][v]);
        }
        __syncthreads();
    }
#pragma unroll
    for (int u = 0; u < 4; u++)
#pragma unroll
        for (int v = 0; v < 4; v++) {
            int m = m0 + ty * 4 + u, h = h0 + tx * 4 + v;
            g_xw[(size_t)m * HH + h] = acc[u][v] + b_aff[h];
        }
}

// ---------------- persistent step kernel -----------------------------------
#define BSTR 65   // Bsd row stride in ull (64 batch slots + 1 pad)
__global__ __launch_bounds__(256) void persistent_kernel(
        const int* __restrict__ lengths, const float* __restrict__ b_eff,
        float* __restrict__ out, int N, int writeSteps) {
    extern __shared__ ull dynsmem[];
    ull* Asd = dynsmem;                    // [256 k][32] : idx j*8+hg -> pair {h,h+1}
    ull* Bsd = dynsmem + 256 * 32;         // [32 k][BSTR] : idx b -> dup {v,v}
    __shared__ int   rowOff[BB];
    __shared__ __align__(16) float sh_hdel[HH];
    __shared__ float sval[VV];
    __shared__ int   sidx[VV];

    int tid = threadIdx.x, cta = blockIdx.x;
    int dd = cta >> 2, hb = cta & 3, h0 = hb * 64;
    int hg = tid & 7, bg = tid >> 3;       // thread: h = h0+hg*8..+7, b = bg*2,+1
    int r = tid >> 2, kq = tid & 3;        // B loader: batch r, k-quarter kq

    // one-time: pack cw tile into smem as h-pairs [k][j*8+hg]
    {
        const float* cwd = g_cw + (size_t)dd * HH * INN;
        for (int idx = tid; idx < 256 * 32; idx += 256) {
            int k = idx >> 5, p = idx & 31;
            int j = p >> 3, hgl = p & 7;
            int h = h0 + hgl * 8 + j * 2;
            Asd[idx] = pkf2(cwd[(size_t)h * INN + k], cwd[(size_t)(h + 1) * INN + k]);
        }
    }
    __syncthreads();

    int lenb = (cta < BB) ? lengths[cta] : 0;
    unsigned ph = 0;
    int TS = TT + 9 + N;

    for (int step = 0; step < TS; step++) {
        // ---- K1 ----
        if (tid < BB) {
            int tb = __ldcg(&g_tau[tid]);
            rowOff[tid] = tid * (NDLY * HH) + (((tb - (dd + 1)) & 31) * HH);
        }
        __syncthreads();
        ull acc[4][2];
#pragma unroll
        for (int j = 0; j < 4; j++) { acc[j][0] = 0ull; acc[j][1] = 0ull; }
        int brow = rowOff[r];
        for (int k0 = 0; k0 < 256; k0 += 32) {
            const float4* bp = (const float4*)(g_hist + brow + k0 + kq * 8);
            float4 bv0 = __ldcg(bp);
            float4 bv1 = __ldcg(bp + 1);
            if (k0) __syncthreads();
            float bv[8] = {bv0.x, bv0.y, bv0.z, bv0.w, bv1.x, bv1.y, bv1.z, bv1.w};
#pragma unroll
            for (int j = 0; j < 8; j++)
                Bsd[(size_t)(kq * 8 + j) * BSTR + r] = pkf2(bv[j], bv[j]);
            __syncthreads();
#pragma unroll
            for (int k = 0; k < 32; k++) {
                const ull* arow = Asd + (size_t)(k0 + k) * 32;
                ull a0 = arow[0 * 8 + hg];
                ull a1 = arow[1 * 8 + hg];
                ull a2 = arow[2 * 8 + hg];
                ull a3 = arow[3 * 8 + hg];
                const ull* brw = Bsd + (size_t)k * BSTR;
                ull b0 = brw[bg * 2 + 0];
                ull b1 = brw[bg * 2 + 1];
                acc[0][0] = ffma2(a0, b0, acc[0][0]);
                acc[1][0] = ffma2(a1, b0, acc[1][0]);
                acc[2][0] = ffma2(a2, b0, acc[2][0]);
                acc[3][0] = ffma2(a3, b0, acc[3][0]);
                acc[0][1] = ffma2(a0, b1, acc[0][1]);
                acc[1][1] = ffma2(a1, b1, acc[1][1]);
                acc[2][1] = ffma2(a2, b1, acc[2][1]);
                acc[3][1] = ffma2(a3, b1, acc[3][1]);
            }
        }
        {
            float* P = g_partial + (size_t)dd * BH;
#pragma unroll
            for (int c = 0; c < 2; c++) {
                int b = bg * 2 + c;
                float2 v0 = upkf2(acc[0][c]), v1 = upkf2(acc[1][c]);
                float2 v2 = upkf2(acc[2][c]), v3 = upkf2(acc[3][c]);
                float4* dst = (float4*)(P + (size_t)b * HH + h0 + hg * 8);
                dst[0] = make_float4(v0.x, v0.y, v1.x, v1.y);
                dst[1] = make_float4(v2.x, v2.y, v3.x, v3.y);
            }
        }
        gsync(ph);

        // ---- K2 ----
        if (cta < BB) {
            int b = cta;
            float acc2 = 0.0f;
            for (int s = NDLY - 1; s >= 0; --s)
                acc2 += __ldcg(&g_partial[(size_t)s * BH + b * HH + tid]);

            if (step < TT) {
                int t = step;
                float hv = xla_tanh(g_xw[(size_t)(b * TT + t) * HH + tid] + acc2);
                if (t < lenb) {
                    g_hist[b * (NDLY * HH) + (t & 31) * HH + tid] = hv;
                    if (tid == 0) g_tau[b] = t + 1;
                }
            } else {
                int g = step - TT;
                int ci = g_curIdx[b], myTau = g_tau[b], myDone = g_done[b];
                int mySteps = g_stepsA[b];

                sh_hdel[tid] = acc2;
                __syncthreads();

                // y = w_eff @ h_del + b_eff via h-pair-packed transposed weights
                const ull* hdl = (const ull*)sh_hdel;
                ull ya = 0ull, yb = 0ull;
#pragma unroll 8
                for (int h2 = 0; h2 < HH / 2; h2 += 2) {
                    ya = ffma2(g_weT2[(size_t)h2 * VV + tid],       hdl[h2],     ya);
                    yb = ffma2(g_weT2[(size_t)(h2 + 1) * VV + tid], hdl[h2 + 1], yb);
                }
                float2 pa = upkf2(ya), pb = upkf2(yb);
                float y = ((pa.x + pa.y) + (pb.x + pb.y)) + b_eff[tid];

                unsigned kv = (g < 9) ? (unsigned)g : (unsigned)(1000 + (g - 9));
                unsigned f0, f1;
                tf2x32(g_keys[2 * b], g_keys[2 * b + 1], 0u, kv, f0, f1);
                unsigned o0, o1;
                tf2x32(f0, f1, 0u, (unsigned)tid, o0, o1);
                unsigned bits = o0 ^ o1;

                const float TINY = 1.17549435e-38f;
                float fm = __uint_as_float((bits >> 9) | 0x3F800000u) - 1.0f;
                float uu = fmaxf(TINY, fm * (1.0f - TINY) + TINY);
                float gum = -logf(-logf(uu));

                sval[tid] = y + gum; sidx[tid] = tid;
                __syncthreads();
                for (int off = 128; off > 0; off >>= 1) {
                    if (tid < off) {
                        float v2 = sval[tid + off]; int i2 = sidx[tid + off];
                        if (v2 > sval[tid] || (v2 == sval[tid] && i2 < sidx[tid])) {
                            sval[tid] = v2; sidx[tid] = i2;
                        }
                    }
                    __syncthreads();
                }
                int amax = sidx[0];

                float xin = (ci < 0) ? g_xw[(size_t)(b * TT + (lenb - 1)) * HH + tid]
                                     : g_wa1[ci * HH + tid];
                float hv = xla_tanh(xin + sh_hdel[tid]);

                bool thinkPh = (g < 9);
                bool adv = thinkPh ? (myDone == 0) : true;
                if (adv) g_hist[b * (NDLY * HH) + (myTau & 31) * HH + tid] = hv;

                if (!thinkPh) {
                    int k = g - 9;
                    if (tid < VV - 1)
                        out[((size_t)b * N + k) * (VV - 1) + tid] = y;
                }
                if (tid == 0) {
                    if (thinkPh) {
                        int nst = mySteps + (myDone ? 0 : 1);
                        int nd = (myDone || amax == (VV - 1) || nst > 8) ? 1 : 0;
                        g_stepsA[b] = nst; g_done[b] = nd;
                        if (!myDone) { g_tau[b] = myTau + 1; g_curIdx[b] = amax; }
                        if (g == 8 && writeSteps)
                            out[(size_t)BB * N * (VV - 1) + b] = (float)nst;
                    } else {
                        g_tau[b] = myTau + 1; g_curIdx[b] = amax;
                    }
                }
            }
        }
        gsync(ph);
    }
}

extern "C" void kernel_launch(void* const* d_in, const int* in_sizes, int n_in,
                              void* d_out, int out_size) {
    const float* x       = (const float*)d_in[0];
    const float* w_aff   = (const float*)d_in[1];
    const float* b_aff   = (const float*)d_in[2];
    const float* lateral = (const float*)d_in[3];
    const float* tau     = (const float*)d_in[4];
    const float* w_eff   = (const float*)d_in[5];
    const float* b_eff   = (const float*)d_in[6];
    const int*   lengths = (const int*)d_in[7];
    (void)n_in; (void)in_sizes;
    float* out = (float*)d_out;

    int Vm1 = VV - 1;
    int N, writeSteps;
    if (out_size % (BB * Vm1) == 0) { N = out_size / (BB * Vm1); writeSteps = 0; }
    else { N = (out_size - BB) / (BB * Vm1); writeSteps = 1; }

    int dynBytes = (256 * 32 + 32 * BSTR) * (int)sizeof(ull);   // 82176
    cudaFuncSetAttribute(persistent_kernel,
                         cudaFuncAttributeMaxDynamicSharedMemorySize, dynBytes);

    init_state_kernel<<<(BB * NDLY * HH + 255) / 256, 256>>>();
    keys_kernel<<<1, 64>>>();
    build_cw_kernel<<<(NDLY * HH * INN) / 256, 256>>>(lateral, tau);
    build_aux_kernel<<<(INN * HH) / 256, 256>>>(w_aff, b_aff, w_eff);
    xw_gemm_kernel<<<dim3((BB * TT) / 64, HH / 64), 256>>>(x, w_aff, b_aff);

    persistent_kernel<<<GRID, 256, dynBytes>>>(lengths, b_eff, out, N, writeSteps);
}